// round 10
// baseline (speedup 1.0000x reference)
#include <cuda_runtime.h>
#include <cuda_bf16.h>
#include <cstdint>

// Problem constants (fixed by the dataset)
#define Bn 16384
#define Dn 2048
#define Hn 512
#define BDn ((size_t)Bn * (size_t)Dn)

// ---------------------------------------------------------------------------
// Scratch (device globals — no allocations allowed)
// ---------------------------------------------------------------------------
__device__ __align__(16) __nv_bfloat16 g_xt[(size_t)128 * 32 * 2 * 8192];  // 128 MB
__device__ __align__(16) __nv_bfloat16 g_wt[(size_t)4 * 32 * 2 * 8192];    // 4 MB
__device__ float g_part[4 * Bn];
__device__ float g_l1[Bn];
__device__ int   g_fixcnt;
__device__ int   g_fixlist[Bn];

// ---------------------------------------------------------------------------
// PTX helpers — base-target (compute_103-safe).
// ---------------------------------------------------------------------------
__device__ __forceinline__ uint32_t smem_u32(const void* p) {
    uint32_t a;
    asm("{ .reg .u64 t; cvta.to.shared.u64 t, %1; cvt.u32.u64 %0, t; }" : "=r"(a) : "l"(p));
    return a;
}
#define MBAR_INIT(a, n) asm volatile("mbarrier.init.shared.b64 [%0], %1;" :: "r"(a), "r"(n) : "memory")
#define MBAR_EXPECT(a, bytes) \
    asm volatile("mbarrier.arrive.expect_tx.shared.b64 _, [%0], %1;" :: "r"(a), "r"(bytes) : "memory")
#define MBAR_WAIT(a, p) do { \
    uint32_t _m = (a), _p = (p), _d; \
    asm volatile("{ .reg .pred q; mbarrier.try_wait.parity.acquire.cta.shared::cta.b64 q, [%1], %2; selp.b32 %0,1,0,q; }" \
                 : "=r"(_d) : "r"(_m), "r"(_p) : "memory"); \
    if (!_d) { \
        asm volatile("{ .reg .pred Q;\nWL_%=:\nmbarrier.try_wait.parity.acquire.cta.shared::cta.b64 Q, [%0], %1, 0x989680;\n@Q bra.uni WD_%=;\nbra.uni WL_%=;\nWD_%=:\n}" \
                     :: "r"(_m), "r"(_p) : "memory"); \
    } } while (0)
#define BULK_G2S(dst, src, sz, mb_) \
    asm volatile("cp.async.bulk.shared::cta.global.mbarrier::complete_tx::bytes [%0], [%1], %2, [%3];" \
                 :: "r"(dst), "l"(src), "r"(sz), "r"(mb_) : "memory")

#define LDSM4(r, a) \
    asm volatile("ldmatrix.sync.aligned.m8n8.x4.shared.b16 {%0,%1,%2,%3}, [%4];" \
        : "=r"((r)[0]), "=r"((r)[1]), "=r"((r)[2]), "=r"((r)[3]) : "r"(a))

__device__ __forceinline__ void mma16816(float* c, const uint32_t* a,
                                         uint32_t b0, uint32_t b1) {
    asm volatile("mma.sync.aligned.m16n8k16.row.col.f32.bf16.bf16.f32 "
        "{%0,%1,%2,%3},{%4,%5,%6,%7},{%8,%9},{%0,%1,%2,%3};"
        : "+f"(c[0]), "+f"(c[1]), "+f"(c[2]), "+f"(c[3])
        : "r"(a[0]), "r"(a[1]), "r"(a[2]), "r"(a[3]), "r"(b0), "r"(b1));
}

// ---------------------------------------------------------------------------
// Kernel 1: convert x -> (hi, lo) bf16 split, TILED+SWIZZLED. Zeroes fixcnt.
// ---------------------------------------------------------------------------
__global__ __launch_bounds__(256)
void convert_x_kernel(const float* __restrict__ x)
{
    if (blockIdx.x == 0 && threadIdx.x == 0) g_fixcnt = 0;
    size_t i = ((size_t)blockIdx.x * 256 + threadIdx.x) * 8;
    float4 a = *(const float4*)(x + i);
    float4 b = *(const float4*)(x + i + 4);
    float v[8] = {a.x, a.y, a.z, a.w, b.x, b.y, b.z, b.w};
    __align__(16) __nv_bfloat16 h[8], l[8];
#pragma unroll
    for (int j = 0; j < 8; j++) {
        h[j] = __float2bfloat16_rn(v[j]);
        l[j] = __float2bfloat16_rn(v[j] - __bfloat162float(h[j]));
    }
    const int R = (int)(i >> 11), K = (int)(i & 2047);
    const int mb = R >> 7, r = R & 127;
    const int kc = K >> 6, g = (K & 63) >> 3;
    const size_t base = ((size_t)(mb * 32 + kc) * 2) * 8192
                      + (size_t)(r * 64 + ((g ^ (r & 7)) * 8));
    *(uint4*)(g_xt + base)        = *(uint4*)h;
    *(uint4*)(g_xt + base + 8192) = *(uint4*)l;
}

// ---------------------------------------------------------------------------
// Kernel 2: transpose + split W1 -> tiled+swizzled W^T bf16 hi/lo.
// ---------------------------------------------------------------------------
__global__ void convert_w_kernel(const float* __restrict__ W1)
{
    __shared__ float tile[32][33];
    const int kb = blockIdx.x * 32, nb0 = blockIdx.y * 32;
    const int tx = threadIdx.x, ty = threadIdx.y;
#pragma unroll
    for (int i = 0; i < 32; i += 8)
        tile[ty + i][tx] = W1[(size_t)(kb + ty + i) * Hn + nb0 + tx];
    __syncthreads();

    const int tid = ty * 32 + tx;
    const int nn  = tid >> 3;
    const int sub = tid & 7;
    const int n   = nb0 + nn;
    const int nbi = n >> 7, rr = n & 127;
    const int k0  = kb + sub * 4;
    const int kc  = k0 >> 6, g = (k0 & 63) >> 3, e = k0 & 7;

    __align__(8) __nv_bfloat16 h[4], l[4];
#pragma unroll
    for (int j = 0; j < 4; j++) {
        float v = tile[sub * 4 + j][nn];
        h[j] = __float2bfloat16_rn(v);
        l[j] = __float2bfloat16_rn(v - __bfloat162float(h[j]));
    }
    const size_t base = ((size_t)(nbi * 32 + kc) * 2) * 8192
                      + (size_t)(rr * 64 + ((g ^ (rr & 7)) * 8) + e);
    *(uint64_t*)(g_wt + base)        = *(uint64_t*)h;
    *(uint64_t*)(g_wt + base + 8192) = *(uint64_t*)l;
}

// ---------------------------------------------------------------------------
// Kernel 3: warp-MMA bf16 GEMM (unchanged; measured 71.5% tensor, 238us).
// ---------------------------------------------------------------------------
#define TILE_B  16384
#define STAGEB  (4 * TILE_B)
#define NSTG    3
#define NCHUNK  32
#define DSMEM   (NSTG * STAGEB)

__global__ __launch_bounds__(256, 1)
void mma_gemm_kernel(const float* __restrict__ b1,
                     const float* __restrict__ W2)
{
    extern __shared__ __align__(128) char dsm[];
    __shared__ __align__(8) unsigned long long s_mbar[NSTG];
    __shared__ float rs[128][4];

    const int t = threadIdx.x;
    const int w = t >> 5, lane = t & 31;
    const int mb = blockIdx.x;
    const int nb = blockIdx.y;
    const int warp_m = (w >> 2) * 64;
    const int warp_n = (w & 3) * 32;

    const uint32_t stage0 = smem_u32(dsm);
    uint32_t mbar[NSTG];
#pragma unroll
    for (int s = 0; s < NSTG; s++) mbar[s] = smem_u32(&s_mbar[s]);

    if (t == 0) {
#pragma unroll
        for (int s = 0; s < NSTG; s++) MBAR_INIT(mbar[s], 1);
    }
    __syncthreads();

    const __nv_bfloat16* gA = g_xt + ((size_t)mb * 32) * 2 * 8192;
    const __nv_bfloat16* gB = g_wt + ((size_t)nb * 32) * 2 * 8192;

#define ISSUE(nc) do { \
        const uint32_t _st = stage0 + (uint32_t)(((nc) % NSTG) * STAGEB); \
        MBAR_EXPECT(mbar[(nc) % NSTG], (uint32_t)STAGEB); \
        BULK_G2S(_st,              gA + (size_t)(nc) * 2 * 8192, 2 * TILE_B, mbar[(nc) % NSTG]); \
        BULK_G2S(_st + 2 * TILE_B, gB + (size_t)(nc) * 2 * 8192, 2 * TILE_B, mbar[(nc) % NSTG]); \
    } while (0)

    if (t == 0) { ISSUE(0); ISSUE(1); ISSUE(2); }

    const int rA  = (lane & 7) + ((lane >> 3) & 1) * 8;
    const int gA4 = (lane >> 4) & 1;
    const int rB  = (lane & 7) + ((lane >> 4) & 1) * 8;
    const int gB4 = (lane >> 3) & 1;
    const int rxa = (warp_m + rA) & 7;
    const int rxb = (warp_n + rB) & 7;
    const uint32_t aRow = (uint32_t)(warp_m + rA) * 128;
    const uint32_t bRow = (uint32_t)(warp_n + rB) * 128;

    float biasv[8], w2v[8];
#pragma unroll
    for (int fn = 0; fn < 4; fn++)
#pragma unroll
        for (int e = 0; e < 2; e++) {
            const int colg = nb * 128 + warp_n + 8 * fn + 2 * (lane & 3) + e;
            biasv[fn * 2 + e] = __ldg(&b1[colg]);
            w2v[fn * 2 + e]   = __ldg(&W2[colg]);
        }

    float acc[4][4][4];
#pragma unroll
    for (int i = 0; i < 4; i++)
#pragma unroll
        for (int j = 0; j < 4; j++)
#pragma unroll
            for (int q = 0; q < 4; q++) acc[i][j][q] = 0.f;

    for (int cc = 0; cc < NCHUNK; cc++) {
        MBAR_WAIT(mbar[cc % NSTG], (cc / NSTG) & 1);
        const uint32_t st = stage0 + (uint32_t)((cc % NSTG) * STAGEB);
        const uint32_t stAhi = st, stAlo = st + TILE_B;
        const uint32_t stBhi = st + 2 * TILE_B, stBlo = st + 3 * TILE_B;

#pragma unroll
        for (int kk = 0; kk < 4; kk++) {
            const uint32_t gaOff = (uint32_t)(((kk * 2 + gA4) ^ rxa) << 4);
            const uint32_t gbOff = (uint32_t)(((kk * 2 + gB4) ^ rxb) << 4);
            uint32_t ah[4][4], al[4][4], bh[2][4], bl[2][4];
#pragma unroll
            for (int fm = 0; fm < 4; fm++) {
                LDSM4(ah[fm], stAhi + aRow + fm * 2048 + gaOff);
                LDSM4(al[fm], stAlo + aRow + fm * 2048 + gaOff);
            }
#pragma unroll
            for (int fp = 0; fp < 2; fp++) {
                LDSM4(bh[fp], stBhi + bRow + fp * 2048 + gbOff);
                LDSM4(bl[fp], stBlo + bRow + fp * 2048 + gbOff);
            }
#pragma unroll
            for (int fm = 0; fm < 4; fm++)
#pragma unroll
                for (int fn = 0; fn < 4; fn++) {
                    const int fp = fn >> 1, hb = (fn & 1) * 2;
                    mma16816(acc[fm][fn], ah[fm], bh[fp][hb], bh[fp][hb + 1]);
                }
#pragma unroll
            for (int fm = 0; fm < 4; fm++)
#pragma unroll
                for (int fn = 0; fn < 4; fn++) {
                    const int fp = fn >> 1, hb = (fn & 1) * 2;
                    mma16816(acc[fm][fn], ah[fm], bl[fp][hb], bl[fp][hb + 1]);
                }
#pragma unroll
            for (int fm = 0; fm < 4; fm++)
#pragma unroll
                for (int fn = 0; fn < 4; fn++) {
                    const int fp = fn >> 1, hb = (fn & 1) * 2;
                    mma16816(acc[fm][fn], al[fm], bh[fp][hb], bh[fp][hb + 1]);
                }
        }
        __syncthreads();
        if (t == 0 && cc + NSTG < NCHUNK) ISSUE(cc + NSTG);
    }

#pragma unroll
    for (int fm = 0; fm < 4; fm++) {
        float s0 = 0.f, s1 = 0.f;
#pragma unroll
        for (int fn = 0; fn < 4; fn++)
#pragma unroll
            for (int e = 0; e < 2; e++) {
                s0 += fmaxf(acc[fm][fn][e]     + biasv[fn * 2 + e], 0.f) * w2v[fn * 2 + e];
                s1 += fmaxf(acc[fm][fn][2 + e] + biasv[fn * 2 + e], 0.f) * w2v[fn * 2 + e];
            }
        s0 += __shfl_xor_sync(0xffffffffu, s0, 1);
        s0 += __shfl_xor_sync(0xffffffffu, s0, 2);
        s1 += __shfl_xor_sync(0xffffffffu, s1, 1);
        s1 += __shfl_xor_sync(0xffffffffu, s1, 2);
        if ((lane & 3) == 0) {
            rs[warp_m + 16 * fm + (lane >> 2)][w & 3]     = s0;
            rs[warp_m + 16 * fm + 8 + (lane >> 2)][w & 3] = s1;
        }
    }
    __syncthreads();
    if (t < 128)
        g_part[(size_t)nb * Bn + mb * 128 + t] = rs[t][0] + rs[t][1] + rs[t][2] + rs[t][3];
#undef ISSUE
}

// ---------------------------------------------------------------------------
// Warp-wide 256-bin histogram select: find bin containing the kt-th count
// and the remainder within it. hist is this warp's private 256-bin array.
// ---------------------------------------------------------------------------
__device__ __forceinline__ void warp_hist_select(const int* h, int kt, int lane,
                                                 int& bin, int& rem)
{
    int c[8], tot = 0;
#pragma unroll
    for (int j = 0; j < 8; j++) { c[j] = h[lane * 8 + j]; tot += c[j]; }
    int incl = tot;
#pragma unroll
    for (int o = 1; o < 32; o <<= 1) {
        int n = __shfl_up_sync(0xffffffffu, incl, o);
        if (lane >= o) incl += n;
    }
    const int excl = incl - tot;
    const bool own = (excl < kt) && (kt <= incl);
    const unsigned bal = __ballot_sync(0xffffffffu, own);
    const int src = __ffs(bal) - 1;
    int b = -1, rm = 0;
    if (own) {
        int run = excl;
#pragma unroll
        for (int j = 0; j < 8; j++) {
            if (b < 0 && run + c[j] >= kt) { b = lane * 8 + j; rm = kt - run; }
            run += c[j];
        }
    }
    bin = __shfl_sync(0xffffffffu, b, src);
    rem = __shfl_sync(0xffffffffu, rm, src);
}

// ---------------------------------------------------------------------------
// Kernel 4 (PROFILED SLOT): warp-per-row select. NO block barriers.
// Each warp: sp/k from g_part, 64 elems/lane in regs, warp-private hist,
// 2x 8-bit passes, candidate rank-resolve, outputs. Boundary rows flagged
// to g_fixlist for exact redo in fix_select_kernel.
// ---------------------------------------------------------------------------
__global__ __launch_bounds__(256)
void select_warp_kernel(const float* __restrict__ x,
                        const float* __restrict__ b2,
                        float* __restrict__ out,
                        float* __restrict__ gl1)
{
    __shared__ int      hist[8][256];
    __shared__ unsigned cand[8][256];
    __shared__ int      candcnt[8];
    __shared__ unsigned sthr[8];

    const int w = threadIdx.x >> 5, lane = threadIdx.x & 31;
    const int r = blockIdx.x * 8 + w;
    const size_t base = (size_t)r * Dn;
    const unsigned FULL = 0xffffffffu;

    // ---- sp / k (all lanes compute identically; lane0 writes/flags) ----
    float s = g_part[r] + g_part[Bn + r] + g_part[2 * Bn + r] + g_part[3 * Bn + r];
    float logit = s + b2[0];
    float sig = 1.f / (1.f + expf(-logit));
    float sp  = 0.05f + 0.25f * sig;
    float kf  = 2048.f * (1.f - sp);
    int kt = (int)rintf(kf);
    if (kt < 1) kt = 1;
    if (lane == 0) {
        out[2 * BDn + r] = sp;
        float frac = kf - floorf(kf);
        if (fabsf(frac - 0.5f) < 0.004f) {
            int idx = atomicAdd(&g_fixcnt, 1);
            g_fixlist[idx] = r;
        }
    }

    // ---- load 64 elems/lane (coalesced 512B per warp-iter) ----
    uint4 d[16];
#pragma unroll
    for (int i = 0; i < 16; i++)
        d[i] = *(const uint4*)(x + base + i * 128 + lane * 4);

    // ---- pass 1: bits 31:24 ----
#pragma unroll
    for (int b = 0; b < 8; b++) hist[w][lane * 8 + b] = 0;
    __syncwarp();
#pragma unroll
    for (int i = 0; i < 16; i++) {
        const unsigned kk[4] = { d[i].x & 0x7fffffffu, d[i].y & 0x7fffffffu,
                                 d[i].z & 0x7fffffffu, d[i].w & 0x7fffffffu };
#pragma unroll
        for (int e = 0; e < 4; e++) {
            const int bin = (int)(kk[e] >> 24);
            const unsigned grp = __match_any_sync(FULL, bin);
            if (lane == __ffs(grp) - 1) atomicAdd(&hist[w][bin], __popc(grp));
        }
    }
    __syncwarp();
    int bin1, rem1;
    warp_hist_select(hist[w], kt, lane, bin1, rem1);
    __syncwarp();

    // ---- pass 2: bits 23:16 among keys with top byte == bin1 ----
#pragma unroll
    for (int b = 0; b < 8; b++) hist[w][lane * 8 + b] = 0;
    if (lane == 0) candcnt[w] = 0;
    __syncwarp();
#pragma unroll
    for (int i = 0; i < 16; i++) {
        const unsigned kk[4] = { d[i].x & 0x7fffffffu, d[i].y & 0x7fffffffu,
                                 d[i].z & 0x7fffffffu, d[i].w & 0x7fffffffu };
#pragma unroll
        for (int e = 0; e < 4; e++) {
            const bool act = ((int)(kk[e] >> 24) == bin1);
            const int bin = act ? (int)((kk[e] >> 16) & 0xFF) : -1;
            const unsigned grp = __match_any_sync(FULL, bin);
            if (act && lane == __ffs(grp) - 1) atomicAdd(&hist[w][bin], __popc(grp));
        }
    }
    __syncwarp();
    int bin2, rem2;
    warp_hist_select(hist[w], rem1, lane, bin2, rem2);
    __syncwarp();

    // ---- candidates with 16-bit prefix; exact rank-select ----
    const unsigned pref16 = ((unsigned)bin1 << 8) | (unsigned)bin2;
#pragma unroll
    for (int i = 0; i < 16; i++) {
        const unsigned kk[4] = { d[i].x & 0x7fffffffu, d[i].y & 0x7fffffffu,
                                 d[i].z & 0x7fffffffu, d[i].w & 0x7fffffffu };
#pragma unroll
        for (int e = 0; e < 4; e++) {
            if ((kk[e] >> 16) == pref16) {
                int idx = atomicAdd(&candcnt[w], 1);
                if (idx < 256) cand[w][idx] = kk[e];
            }
        }
    }
    __syncwarp();
    {
        const int c = min(candcnt[w], 256);
        for (int i = lane; i < c; i += 32) {
            const unsigned me = cand[w][i];
            int rank = 0, eq = 0;
            for (int j = 0; j < c; j++) {
                const unsigned kj = cand[w][j];
                rank += (kj < me);
                eq   += (kj == me);
            }
            if (rank < rem2 && rem2 <= rank + eq) sthr[w] = me;
        }
    }
    __syncwarp();
    const unsigned thr = sthr[w];

    // ---- outputs ----
    int cnt = 0;
    float l1 = 0.f;
#pragma unroll
    for (int i = 0; i < 16; i++) {
        const unsigned kk[4] = { d[i].x & 0x7fffffffu, d[i].y & 0x7fffffffu,
                                 d[i].z & 0x7fffffffu, d[i].w & 0x7fffffffu };
        float sx[4], mk[4];
        const unsigned raw[4] = { d[i].x, d[i].y, d[i].z, d[i].w };
#pragma unroll
        for (int e = 0; e < 4; e++) {
            const bool keep = kk[e] > thr;
            sx[e] = keep ? __uint_as_float(raw[e]) : 0.f;
            mk[e] = keep ? 1.f : 0.f;
            cnt += keep ? 1 : 0;
            l1  += keep ? __uint_as_float(kk[e]) : 0.f;
        }
        *(float4*)(out + base + i * 128 + lane * 4)       = make_float4(sx[0], sx[1], sx[2], sx[3]);
        *(float4*)(out + BDn + base + i * 128 + lane * 4) = make_float4(mk[0], mk[1], mk[2], mk[3]);
    }
#pragma unroll
    for (int o = 16; o > 0; o >>= 1) {
        cnt += __shfl_down_sync(FULL, cnt, o);
        l1  += __shfl_down_sync(FULL, l1, o);
    }
    if (lane == 0) {
        out[2 * BDn + Bn + r] = (float)cnt * (1.0f / 2048.0f);
        gl1[r] = l1;
    }
}

// ---------------------------------------------------------------------------
// Kernel 5: exact redo of flagged boundary rows (block-per-row, fp32 logit,
// full block-wide radix select; overwrites all per-row outputs).
// ---------------------------------------------------------------------------
__global__ __launch_bounds__(256)
void fix_select_kernel(const float* __restrict__ x,
                       const float* __restrict__ W1,
                       const float* __restrict__ b1,
                       const float* __restrict__ W2,
                       const float* __restrict__ b2,
                       float* __restrict__ out,
                       float* __restrict__ gl1)
{
    __shared__ unsigned buf[2048];
    __shared__ int hist[256];
    __shared__ int warpsum[8];
    __shared__ int warpoff[8];
    __shared__ int s_bin, s_rem, s_cnt, s_k;
    __shared__ float sred[8];
    __shared__ unsigned s_thr;
    __shared__ int scnt[8];
    __shared__ float sl1[8];

    const int cntrows = g_fixcnt;
    const int t = threadIdx.x;
    const int lane = t & 31, w = t >> 5;

    for (int it = blockIdx.x; it < cntrows; it += gridDim.x) {
        const int r = g_fixlist[it];
        const size_t base = (size_t)r * Dn;

        float xv[8];
        {
            float4 a = *(const float4*)(x + base + 8 * t);
            float4 b = *(const float4*)(x + base + 8 * t + 4);
            xv[0] = a.x; xv[1] = a.y; xv[2] = a.z; xv[3] = a.w;
            xv[4] = b.x; xv[5] = b.y; xv[6] = b.z; xv[7] = b.w;
        }
        unsigned kb[8];
#pragma unroll
        for (int i = 0; i < 8; i++) kb[i] = __float_as_uint(fabsf(xv[i]));

        // exact fp32 logit
        float* xs = (float*)buf;
#pragma unroll
        for (int i = 0; i < 8; i++) xs[8 * t + i] = xv[i];
        __syncthreads();
        float ha = 0.f, hb = 0.f;
#pragma unroll 4
        for (int k = 0; k < Dn; k++) {
            float xk = xs[k];
            ha = fmaf(xk, W1[(size_t)k * Hn + t],       ha);
            hb = fmaf(xk, W1[(size_t)k * Hn + t + 256], hb);
        }
        float p = fmaxf(ha + b1[t], 0.f) * W2[t]
                + fmaxf(hb + b1[t + 256], 0.f) * W2[t + 256];
#pragma unroll
        for (int o = 16; o > 0; o >>= 1) p += __shfl_down_sync(0xffffffffu, p, o);
        if (lane == 0) sred[w] = p;
        __syncthreads();
        if (t == 0) {
            float s = 0.f;
#pragma unroll
            for (int q = 0; q < 8; q++) s += sred[q];
            float logit = s + b2[0];
            float sig = 1.f / (1.f + expf(-logit));
            float sp  = 0.05f + 0.25f * sig;
            int k = (int)rintf(2048.f * (1.f - sp));
            if (k < 1) k = 1;
            out[2 * BDn + r] = sp;
            s_k = k;
        }
        __syncthreads();
        int kt = s_k;

        // two 8-bit radix passes
        unsigned prefix = 0, himask = 0;
#pragma unroll
        for (int pp = 3; pp >= 2; pp--) {
            const int shift = pp * 8;
            hist[t] = 0;
            __syncthreads();
#pragma unroll
            for (int i = 0; i < 8; i++) {
                unsigned key = kb[i];
                bool act = ((key & himask) == prefix);
                int bin = act ? (int)((key >> shift) & 0xFF) : -1;
                unsigned grp = __match_any_sync(0xffffffffu, bin);
                int leader = __ffs(grp) - 1;
                if (act && lane == leader) atomicAdd(&hist[bin], __popc(grp));
            }
            __syncthreads();
            int c = hist[t];
            int v = c;
#pragma unroll
            for (int o = 1; o < 32; o <<= 1) {
                int nn = __shfl_up_sync(0xffffffffu, v, o);
                if (lane >= o) v += nn;
            }
            if (lane == 31) warpsum[w] = v;
            __syncthreads();
            if (t == 0) {
                int run = 0;
#pragma unroll
                for (int q = 0; q < 8; q++) { warpoff[q] = run; run += warpsum[q]; }
            }
            __syncthreads();
            int incl = v + warpoff[w];
            int excl = incl - c;
            if (excl < kt && incl >= kt) { s_bin = t; s_rem = kt - excl; }
            if (t == 0) s_cnt = 0;
            __syncthreads();
            prefix |= ((unsigned)s_bin) << shift;
            kt = s_rem;
            himask |= 0xFFu << shift;
            __syncthreads();
        }

        const unsigned pref16 = prefix >> 16;
#pragma unroll
        for (int i = 0; i < 8; i++) {
            unsigned key = kb[i];
            if ((key >> 16) == pref16) {
                int idx = atomicAdd(&s_cnt, 1);
                buf[idx] = key;
            }
        }
        __syncthreads();
        if (w == 0) {
            const int c = s_cnt;
            for (int i = lane; i < c; i += 32) {
                unsigned me = buf[i];
                int rank = 0, eq = 0;
                for (int j = 0; j < c; j++) {
                    unsigned kj = buf[j];
                    rank += (kj < me);
                    eq   += (kj == me);
                }
                if (rank < kt && kt <= rank + eq) s_thr = me;
            }
        }
        __syncthreads();
        const unsigned thr = s_thr;

        int cnt = 0;
        float l1 = 0.f;
        float sx[8], mk[8];
#pragma unroll
        for (int i = 0; i < 8; i++) {
            bool keep = kb[i] > thr;
            sx[i] = keep ? xv[i] : 0.f;
            mk[i] = keep ? 1.f : 0.f;
            cnt += keep ? 1 : 0;
            l1  += keep ? __uint_as_float(kb[i]) : 0.f;
        }
        *(float4*)(out + base + 8 * t)           = make_float4(sx[0], sx[1], sx[2], sx[3]);
        *(float4*)(out + base + 8 * t + 4)       = make_float4(sx[4], sx[5], sx[6], sx[7]);
        *(float4*)(out + BDn + base + 8 * t)     = make_float4(mk[0], mk[1], mk[2], mk[3]);
        *(float4*)(out + BDn + base + 8 * t + 4) = make_float4(mk[4], mk[5], mk[6], mk[7]);

#pragma unroll
        for (int o = 16; o > 0; o >>= 1) {
            cnt += __shfl_down_sync(0xffffffffu, cnt, o);
            l1  += __shfl_down_sync(0xffffffffu, l1, o);
        }
        if (lane == 0) { scnt[w] = cnt; sl1[w] = l1; }
        __syncthreads();
        if (t == 0) {
            int C = 0; float L = 0.f;
#pragma unroll
            for (int q = 0; q < 8; q++) { C += scnt[q]; L += sl1[q]; }
            out[2 * BDn + Bn + r] = (float)C * (1.0f / 2048.0f);
            gl1[r] = L;
        }
        __syncthreads();
    }
}

// ---------------------------------------------------------------------------
// Kernel 6: deterministic mean of per-row L1 sums.
// ---------------------------------------------------------------------------
__global__ __launch_bounds__(256)
void l1_reduce_kernel(const float* __restrict__ gl1, float* __restrict__ out_l1)
{
    __shared__ double sd[256];
    const int t = threadIdx.x;
    double s = 0.0;
    for (int i = t; i < Bn; i += 256) s += (double)gl1[i];
    sd[t] = s;
    __syncthreads();
#pragma unroll
    for (int off = 128; off > 0; off >>= 1) {
        if (t < off) sd[t] += sd[t + off];
        __syncthreads();
    }
    if (t == 0) out_l1[0] = (float)(sd[0] / (double)Bn);
}

// ---------------------------------------------------------------------------
extern "C" void kernel_launch(void* const* d_in, const int* in_sizes, int n_in,
                              void* d_out, int out_size)
{
    const float* x  = (const float*)d_in[0];
    const float* W1 = (const float*)d_in[1];
    const float* b1 = (const float*)d_in[2];
    const float* W2 = (const float*)d_in[3];
    const float* b2 = (const float*)d_in[4];
    float* out = (float*)d_out;

    float* gl1;
    cudaGetSymbolAddress((void**)&gl1, g_l1);

    cudaFuncSetAttribute(mma_gemm_kernel,
                         cudaFuncAttributeMaxDynamicSharedMemorySize, DSMEM);

    convert_x_kernel<<<Bn * Dn / (256 * 8), 256>>>(x);        // launch 1
    convert_w_kernel<<<dim3(64, 16), dim3(32, 8)>>>(W1);      // launch 2
    mma_gemm_kernel<<<dim3(128, 4), 256, DSMEM>>>(b1, W2);    // launch 3
    select_warp_kernel<<<Bn / 8, 256>>>(x, b2, out, gl1);     // launch 4 -> profiled
    fix_select_kernel<<<256, 256>>>(x, W1, b1, W2, b2, out, gl1);
    l1_reduce_kernel<<<1, 256>>>(gl1, out + 2 * BDn + 2 * (size_t)Bn);
}

// round 11
// speedup vs baseline: 1.4377x; 1.4377x over previous
#include <cuda_runtime.h>
#include <cuda_bf16.h>
#include <cstdint>

// Problem constants (fixed by the dataset)
#define Bn 16384
#define Dn 2048
#define Hn 512
#define BDn ((size_t)Bn * (size_t)Dn)

// ---------------------------------------------------------------------------
// Scratch (device globals — no allocations allowed)
// ---------------------------------------------------------------------------
__device__ __align__(16) __nv_bfloat16 g_xt[(size_t)128 * 32 * 2 * 8192];  // 128 MB
__device__ __align__(16) __nv_bfloat16 g_wt[(size_t)4 * 32 * 2 * 8192];    // 4 MB
__device__ float g_part[4 * Bn];
__device__ float g_l1[Bn];

// ---------------------------------------------------------------------------
// PTX helpers — base-target (compute_103-safe).
// ---------------------------------------------------------------------------
__device__ __forceinline__ uint32_t smem_u32(const void* p) {
    uint32_t a;
    asm("{ .reg .u64 t; cvta.to.shared.u64 t, %1; cvt.u32.u64 %0, t; }" : "=r"(a) : "l"(p));
    return a;
}
#define MBAR_INIT(a, n) asm volatile("mbarrier.init.shared.b64 [%0], %1;" :: "r"(a), "r"(n) : "memory")
#define MBAR_EXPECT(a, bytes) \
    asm volatile("mbarrier.arrive.expect_tx.shared.b64 _, [%0], %1;" :: "r"(a), "r"(bytes) : "memory")
#define MBAR_WAIT(a, p) do { \
    uint32_t _m = (a), _p = (p), _d; \
    asm volatile("{ .reg .pred q; mbarrier.try_wait.parity.acquire.cta.shared::cta.b64 q, [%1], %2; selp.b32 %0,1,0,q; }" \
                 : "=r"(_d) : "r"(_m), "r"(_p) : "memory"); \
    if (!_d) { \
        asm volatile("{ .reg .pred Q;\nWL_%=:\nmbarrier.try_wait.parity.acquire.cta.shared::cta.b64 Q, [%0], %1, 0x989680;\n@Q bra.uni WD_%=;\nbra.uni WL_%=;\nWD_%=:\n}" \
                     :: "r"(_m), "r"(_p) : "memory"); \
    } } while (0)
#define BULK_G2S(dst, src, sz, mb_) \
    asm volatile("cp.async.bulk.shared::cta.global.mbarrier::complete_tx::bytes [%0], [%1], %2, [%3];" \
                 :: "r"(dst), "l"(src), "r"(sz), "r"(mb_) : "memory")

#define LDSM4(r, a) \
    asm volatile("ldmatrix.sync.aligned.m8n8.x4.shared.b16 {%0,%1,%2,%3}, [%4];" \
        : "=r"((r)[0]), "=r"((r)[1]), "=r"((r)[2]), "=r"((r)[3]) : "r"(a))

__device__ __forceinline__ void mma16816(float* c, const uint32_t* a,
                                         uint32_t b0, uint32_t b1) {
    asm volatile("mma.sync.aligned.m16n8k16.row.col.f32.bf16.bf16.f32 "
        "{%0,%1,%2,%3},{%4,%5,%6,%7},{%8,%9},{%0,%1,%2,%3};"
        : "+f"(c[0]), "+f"(c[1]), "+f"(c[2]), "+f"(c[3])
        : "r"(a[0]), "r"(a[1]), "r"(a[2]), "r"(a[3]), "r"(b0), "r"(b1));
}

// ---------------------------------------------------------------------------
// Kernel 1: convert x -> (hi, lo) bf16 split, TILED+SWIZZLED.
// ---------------------------------------------------------------------------
__global__ __launch_bounds__(256)
void convert_x_kernel(const float* __restrict__ x)
{
    size_t i = ((size_t)blockIdx.x * 256 + threadIdx.x) * 8;
    float4 a = *(const float4*)(x + i);
    float4 b = *(const float4*)(x + i + 4);
    float v[8] = {a.x, a.y, a.z, a.w, b.x, b.y, b.z, b.w};
    __align__(16) __nv_bfloat16 h[8], l[8];
#pragma unroll
    for (int j = 0; j < 8; j++) {
        h[j] = __float2bfloat16_rn(v[j]);
        l[j] = __float2bfloat16_rn(v[j] - __bfloat162float(h[j]));
    }
    const int R = (int)(i >> 11), K = (int)(i & 2047);
    const int mb = R >> 7, r = R & 127;
    const int kc = K >> 6, g = (K & 63) >> 3;
    const size_t base = ((size_t)(mb * 32 + kc) * 2) * 8192
                      + (size_t)(r * 64 + ((g ^ (r & 7)) * 8));
    *(uint4*)(g_xt + base)        = *(uint4*)h;
    *(uint4*)(g_xt + base + 8192) = *(uint4*)l;
}

// ---------------------------------------------------------------------------
// Kernel 2: transpose + split W1 -> tiled+swizzled W^T bf16 hi/lo.
// ---------------------------------------------------------------------------
__global__ void convert_w_kernel(const float* __restrict__ W1)
{
    __shared__ float tile[32][33];
    const int kb = blockIdx.x * 32, nb0 = blockIdx.y * 32;
    const int tx = threadIdx.x, ty = threadIdx.y;
#pragma unroll
    for (int i = 0; i < 32; i += 8)
        tile[ty + i][tx] = W1[(size_t)(kb + ty + i) * Hn + nb0 + tx];
    __syncthreads();

    const int tid = ty * 32 + tx;
    const int nn  = tid >> 3;
    const int sub = tid & 7;
    const int n   = nb0 + nn;
    const int nbi = n >> 7, rr = n & 127;
    const int k0  = kb + sub * 4;
    const int kc  = k0 >> 6, g = (k0 & 63) >> 3, e = k0 & 7;

    __align__(8) __nv_bfloat16 h[4], l[4];
#pragma unroll
    for (int j = 0; j < 4; j++) {
        float v = tile[sub * 4 + j][nn];
        h[j] = __float2bfloat16_rn(v);
        l[j] = __float2bfloat16_rn(v - __bfloat162float(h[j]));
    }
    const size_t base = ((size_t)(nbi * 32 + kc) * 2) * 8192
                      + (size_t)(rr * 64 + ((g ^ (rr & 7)) * 8) + e);
    *(uint64_t*)(g_wt + base)        = *(uint64_t*)h;
    *(uint64_t*)(g_wt + base + 8192) = *(uint64_t*)l;
}

// ---------------------------------------------------------------------------
// Kernel 3: warp-MMA bf16 GEMM (unchanged; measured 71.5% tensor, 238us).
// ---------------------------------------------------------------------------
#define TILE_B  16384
#define STAGEB  (4 * TILE_B)
#define NSTG    3
#define NCHUNK  32
#define DSMEM   (NSTG * STAGEB)

__global__ __launch_bounds__(256, 1)
void mma_gemm_kernel(const float* __restrict__ b1,
                     const float* __restrict__ W2)
{
    extern __shared__ __align__(128) char dsm[];
    __shared__ __align__(8) unsigned long long s_mbar[NSTG];
    __shared__ float rs[128][4];

    const int t = threadIdx.x;
    const int w = t >> 5, lane = t & 31;
    const int mb = blockIdx.x;
    const int nb = blockIdx.y;
    const int warp_m = (w >> 2) * 64;
    const int warp_n = (w & 3) * 32;

    const uint32_t stage0 = smem_u32(dsm);
    uint32_t mbar[NSTG];
#pragma unroll
    for (int s = 0; s < NSTG; s++) mbar[s] = smem_u32(&s_mbar[s]);

    if (t == 0) {
#pragma unroll
        for (int s = 0; s < NSTG; s++) MBAR_INIT(mbar[s], 1);
    }
    __syncthreads();

    const __nv_bfloat16* gA = g_xt + ((size_t)mb * 32) * 2 * 8192;
    const __nv_bfloat16* gB = g_wt + ((size_t)nb * 32) * 2 * 8192;

#define ISSUE(nc) do { \
        const uint32_t _st = stage0 + (uint32_t)(((nc) % NSTG) * STAGEB); \
        MBAR_EXPECT(mbar[(nc) % NSTG], (uint32_t)STAGEB); \
        BULK_G2S(_st,              gA + (size_t)(nc) * 2 * 8192, 2 * TILE_B, mbar[(nc) % NSTG]); \
        BULK_G2S(_st + 2 * TILE_B, gB + (size_t)(nc) * 2 * 8192, 2 * TILE_B, mbar[(nc) % NSTG]); \
    } while (0)

    if (t == 0) { ISSUE(0); ISSUE(1); ISSUE(2); }

    const int rA  = (lane & 7) + ((lane >> 3) & 1) * 8;
    const int gA4 = (lane >> 4) & 1;
    const int rB  = (lane & 7) + ((lane >> 4) & 1) * 8;
    const int gB4 = (lane >> 3) & 1;
    const int rxa = (warp_m + rA) & 7;
    const int rxb = (warp_n + rB) & 7;
    const uint32_t aRow = (uint32_t)(warp_m + rA) * 128;
    const uint32_t bRow = (uint32_t)(warp_n + rB) * 128;

    float biasv[8], w2v[8];
#pragma unroll
    for (int fn = 0; fn < 4; fn++)
#pragma unroll
        for (int e = 0; e < 2; e++) {
            const int colg = nb * 128 + warp_n + 8 * fn + 2 * (lane & 3) + e;
            biasv[fn * 2 + e] = __ldg(&b1[colg]);
            w2v[fn * 2 + e]   = __ldg(&W2[colg]);
        }

    float acc[4][4][4];
#pragma unroll
    for (int i = 0; i < 4; i++)
#pragma unroll
        for (int j = 0; j < 4; j++)
#pragma unroll
            for (int q = 0; q < 4; q++) acc[i][j][q] = 0.f;

    for (int cc = 0; cc < NCHUNK; cc++) {
        MBAR_WAIT(mbar[cc % NSTG], (cc / NSTG) & 1);
        const uint32_t st = stage0 + (uint32_t)((cc % NSTG) * STAGEB);
        const uint32_t stAhi = st, stAlo = st + TILE_B;
        const uint32_t stBhi = st + 2 * TILE_B, stBlo = st + 3 * TILE_B;

#pragma unroll
        for (int kk = 0; kk < 4; kk++) {
            const uint32_t gaOff = (uint32_t)(((kk * 2 + gA4) ^ rxa) << 4);
            const uint32_t gbOff = (uint32_t)(((kk * 2 + gB4) ^ rxb) << 4);
            uint32_t ah[4][4], al[4][4], bh[2][4], bl[2][4];
#pragma unroll
            for (int fm = 0; fm < 4; fm++) {
                LDSM4(ah[fm], stAhi + aRow + fm * 2048 + gaOff);
                LDSM4(al[fm], stAlo + aRow + fm * 2048 + gaOff);
            }
#pragma unroll
            for (int fp = 0; fp < 2; fp++) {
                LDSM4(bh[fp], stBhi + bRow + fp * 2048 + gbOff);
                LDSM4(bl[fp], stBlo + bRow + fp * 2048 + gbOff);
            }
#pragma unroll
            for (int fm = 0; fm < 4; fm++)
#pragma unroll
                for (int fn = 0; fn < 4; fn++) {
                    const int fp = fn >> 1, hb = (fn & 1) * 2;
                    mma16816(acc[fm][fn], ah[fm], bh[fp][hb], bh[fp][hb + 1]);
                }
#pragma unroll
            for (int fm = 0; fm < 4; fm++)
#pragma unroll
                for (int fn = 0; fn < 4; fn++) {
                    const int fp = fn >> 1, hb = (fn & 1) * 2;
                    mma16816(acc[fm][fn], ah[fm], bl[fp][hb], bl[fp][hb + 1]);
                }
#pragma unroll
            for (int fm = 0; fm < 4; fm++)
#pragma unroll
                for (int fn = 0; fn < 4; fn++) {
                    const int fp = fn >> 1, hb = (fn & 1) * 2;
                    mma16816(acc[fm][fn], al[fm], bh[fp][hb], bh[fp][hb + 1]);
                }
        }
        __syncthreads();
        if (t == 0 && cc + NSTG < NCHUNK) ISSUE(cc + NSTG);
    }

#pragma unroll
    for (int fm = 0; fm < 4; fm++) {
        float s0 = 0.f, s1 = 0.f;
#pragma unroll
        for (int fn = 0; fn < 4; fn++)
#pragma unroll
            for (int e = 0; e < 2; e++) {
                s0 += fmaxf(acc[fm][fn][e]     + biasv[fn * 2 + e], 0.f) * w2v[fn * 2 + e];
                s1 += fmaxf(acc[fm][fn][2 + e] + biasv[fn * 2 + e], 0.f) * w2v[fn * 2 + e];
            }
        s0 += __shfl_xor_sync(0xffffffffu, s0, 1);
        s0 += __shfl_xor_sync(0xffffffffu, s0, 2);
        s1 += __shfl_xor_sync(0xffffffffu, s1, 1);
        s1 += __shfl_xor_sync(0xffffffffu, s1, 2);
        if ((lane & 3) == 0) {
            rs[warp_m + 16 * fm + (lane >> 2)][w & 3]     = s0;
            rs[warp_m + 16 * fm + 8 + (lane >> 2)][w & 3] = s1;
        }
    }
    __syncthreads();
    if (t < 128)
        g_part[(size_t)nb * Bn + mb * 128 + t] = rs[t][0] + rs[t][1] + rs[t][2] + rs[t][3];
#undef ISSUE
}

// ---------------------------------------------------------------------------
// Kernel 4 (PROFILED SLOT): fused predictor-final + fixup + single-pass
// 2048-bin radix select (bits 30:20 = 11 bits), then exact candidate
// rank-resolve over the winning bin (~100 keys for N(0,1) rows).
// ---------------------------------------------------------------------------
__global__ __launch_bounds__(256)
void select_kernel(const float* __restrict__ x,
                   const float* __restrict__ W1,
                   const float* __restrict__ b1,
                   const float* __restrict__ W2,
                   const float* __restrict__ b2,
                   float* __restrict__ out,
                   float* __restrict__ gl1)
{
    __shared__ int      hist[2048];     // 11-bit bins
    __shared__ unsigned cand[2048];     // fixup xs (float) / candidate keys
    __shared__ int warpsum[8];
    __shared__ int warpoff[8];
    __shared__ int s_bin, s_rem, s_cnt, s_k, s_flag;
    __shared__ float sred[8];
    __shared__ float s_sp;
    __shared__ unsigned s_thr;
    __shared__ int scnt[8];
    __shared__ float sl1[8];

    const int r = blockIdx.x;
    const int t = threadIdx.x;
    const int lane = t & 31, w = t >> 5;
    const size_t base = (size_t)r * Dn;

    // ---- Phase A: load row ----
    float xv[8];
    {
        float4 a = *(const float4*)(x + base + 8 * t);
        float4 b = *(const float4*)(x + base + 8 * t + 4);
        xv[0] = a.x; xv[1] = a.y; xv[2] = a.z; xv[3] = a.w;
        xv[4] = b.x; xv[5] = b.y; xv[6] = b.z; xv[7] = b.w;
    }
    unsigned kb[8];
#pragma unroll
    for (int i = 0; i < 8; i++) kb[i] = __float_as_uint(fabsf(xv[i]));

    // ---- Phase B: sp/k from GEMM partials; exact fp32 redo on boundary ----
    if (t == 0) {
        float s = g_part[r] + g_part[Bn + r] + g_part[2 * Bn + r] + g_part[3 * Bn + r];
        float logit = s + b2[0];
        float sig = 1.f / (1.f + expf(-logit));
        float sp  = 0.05f + 0.25f * sig;
        float kf  = 2048.f * (1.f - sp);
        int k = (int)rintf(kf);
        if (k < 1) k = 1;
        float frac = kf - floorf(kf);
        s_flag = (fabsf(frac - 0.5f) < 0.004f) ? 1 : 0;
        s_sp = sp; s_k = k;
    }
    __syncthreads();

    if (s_flag) {
        float* xs = (float*)cand;
#pragma unroll
        for (int i = 0; i < 8; i++) xs[8 * t + i] = xv[i];
        __syncthreads();
        float ha = 0.f, hb = 0.f;
#pragma unroll 4
        for (int k = 0; k < Dn; k++) {
            float xk = xs[k];
            ha = fmaf(xk, W1[(size_t)k * Hn + t],       ha);
            hb = fmaf(xk, W1[(size_t)k * Hn + t + 256], hb);
        }
        float p = fmaxf(ha + b1[t], 0.f) * W2[t]
                + fmaxf(hb + b1[t + 256], 0.f) * W2[t + 256];
#pragma unroll
        for (int o = 16; o > 0; o >>= 1) p += __shfl_down_sync(0xffffffffu, p, o);
        if (lane == 0) sred[w] = p;
        __syncthreads();
        if (t == 0) {
            float s = 0.f;
#pragma unroll
            for (int q = 0; q < 8; q++) s += sred[q];
            float logit = s + b2[0];
            float sig = 1.f / (1.f + expf(-logit));
            float sp  = 0.05f + 0.25f * sig;
            int k = (int)rintf(2048.f * (1.f - sp));
            if (k < 1) k = 1;
            s_sp = sp; s_k = k;
        }
        __syncthreads();
    }
    if (t == 0) out[2 * BDn + r] = s_sp;     // sparsity output
    const int kt = s_k;

    // ---- Phase C: single 2048-bin histogram pass (bits 30:20) ----
#pragma unroll
    for (int j = 0; j < 8; j++) hist[8 * t + j] = 0;
    if (t == 0) s_cnt = 0;
    __syncthreads();
#pragma unroll
    for (int i = 0; i < 8; i++) {
        const int bin = (int)(kb[i] >> 20);            // 11 bits (top bit is 0)
        const unsigned grp = __match_any_sync(0xffffffffu, bin);
        if (lane == __ffs(grp) - 1) atomicAdd(&hist[bin], __popc(grp));
    }
    __syncthreads();

    // block scan over 2048 bins; thread t owns bins [8t, 8t+8)
    int c8[8], tot = 0;
#pragma unroll
    for (int j = 0; j < 8; j++) { c8[j] = hist[8 * t + j]; tot += c8[j]; }
    int v = tot;
#pragma unroll
    for (int o = 1; o < 32; o <<= 1) {
        int nn = __shfl_up_sync(0xffffffffu, v, o);
        if (lane >= o) v += nn;
    }
    if (lane == 31) warpsum[w] = v;
    __syncthreads();
    if (t == 0) {
        int run = 0;
#pragma unroll
        for (int q = 0; q < 8; q++) { warpoff[q] = run; run += warpsum[q]; }
    }
    __syncthreads();
    const int incl = v + warpoff[w];
    const int excl = incl - tot;
    if (excl < kt && kt <= incl) {
        int run = excl, b = -1, rm = 0;
#pragma unroll
        for (int j = 0; j < 8; j++) {
            if (b < 0 && run + c8[j] >= kt) { b = 8 * t + j; rm = kt - run; }
            run += c8[j];
        }
        s_bin = b; s_rem = rm;
    }
    __syncthreads();
    const int bin = s_bin;
    const int rem = s_rem;

    // ---- Phase D: gather winning-bin candidates; rank-resolve (all threads) ----
#pragma unroll
    for (int i = 0; i < 8; i++) {
        if ((int)(kb[i] >> 20) == bin) {
            int idx = atomicAdd(&s_cnt, 1);
            cand[idx] = kb[i];
        }
    }
    __syncthreads();
    {
        const int c = s_cnt;
        for (int i = t; i < c; i += 256) {
            const unsigned me = cand[i];
            int rank = 0, eq = 0;
            for (int j = 0; j < c; j++) {
                const unsigned kj = cand[j];
                rank += (kj < me);
                eq   += (kj == me);
            }
            if (rank < rem && rem <= rank + eq) s_thr = me;
        }
    }
    __syncthreads();
    const unsigned thr = s_thr;

    // ---- Phase E: outputs ----
    int cnt = 0;
    float l1 = 0.f;
    float sx[8], mk[8];
#pragma unroll
    for (int i = 0; i < 8; i++) {
        bool keep = kb[i] > thr;
        sx[i] = keep ? xv[i] : 0.f;
        mk[i] = keep ? 1.f : 0.f;
        cnt += keep ? 1 : 0;
        l1  += keep ? __uint_as_float(kb[i]) : 0.f;
    }
    *(float4*)(out + base + 8 * t)           = make_float4(sx[0], sx[1], sx[2], sx[3]);
    *(float4*)(out + base + 8 * t + 4)       = make_float4(sx[4], sx[5], sx[6], sx[7]);
    *(float4*)(out + BDn + base + 8 * t)     = make_float4(mk[0], mk[1], mk[2], mk[3]);
    *(float4*)(out + BDn + base + 8 * t + 4) = make_float4(mk[4], mk[5], mk[6], mk[7]);

#pragma unroll
    for (int o = 16; o > 0; o >>= 1) {
        cnt += __shfl_down_sync(0xffffffffu, cnt, o);
        l1  += __shfl_down_sync(0xffffffffu, l1, o);
    }
    if (lane == 0) { scnt[w] = cnt; sl1[w] = l1; }
    __syncthreads();
    if (t == 0) {
        int C = 0; float L = 0.f;
#pragma unroll
        for (int q = 0; q < 8; q++) { C += scnt[q]; L += sl1[q]; }
        out[2 * BDn + Bn + r] = (float)C * (1.0f / 2048.0f);
        gl1[r] = L;
    }
}

// ---------------------------------------------------------------------------
// Kernel 5: deterministic mean of per-row L1 sums.
// ---------------------------------------------------------------------------
__global__ __launch_bounds__(256)
void l1_reduce_kernel(const float* __restrict__ gl1, float* __restrict__ out_l1)
{
    __shared__ double sd[256];
    const int t = threadIdx.x;
    double s = 0.0;
    for (int i = t; i < Bn; i += 256) s += (double)gl1[i];
    sd[t] = s;
    __syncthreads();
#pragma unroll
    for (int off = 128; off > 0; off >>= 1) {
        if (t < off) sd[t] += sd[t + off];
        __syncthreads();
    }
    if (t == 0) out_l1[0] = (float)(sd[0] / (double)Bn);
}

// ---------------------------------------------------------------------------
extern "C" void kernel_launch(void* const* d_in, const int* in_sizes, int n_in,
                              void* d_out, int out_size)
{
    const float* x  = (const float*)d_in[0];
    const float* W1 = (const float*)d_in[1];
    const float* b1 = (const float*)d_in[2];
    const float* W2 = (const float*)d_in[3];
    const float* b2 = (const float*)d_in[4];
    float* out = (float*)d_out;

    float* gl1;
    cudaGetSymbolAddress((void**)&gl1, g_l1);

    cudaFuncSetAttribute(mma_gemm_kernel,
                         cudaFuncAttributeMaxDynamicSharedMemorySize, DSMEM);

    convert_x_kernel<<<Bn * Dn / (256 * 8), 256>>>(x);       // launch 1
    convert_w_kernel<<<dim3(64, 16), dim3(32, 8)>>>(W1);     // launch 2
    mma_gemm_kernel<<<dim3(128, 4), 256, DSMEM>>>(b1, W2);   // launch 3
    select_kernel<<<Bn, 256>>>(x, W1, b1, W2, b2, out, gl1); // launch 4 -> profiled
    l1_reduce_kernel<<<1, 256>>>(gl1, out + 2 * BDn + 2 * (size_t)Bn);
}